// round 3
// baseline (speedup 1.0000x reference)
#include <cuda_runtime.h>
#include <cstdint>

#define N_NODES 100000
#define N_EDGES 1600000
#define BN_EPS  1e-5f

// ---------------- scratch (static __device__, no allocations) ----------------
__device__ int   g_count[N_NODES];        // in-degree (no self loop)
__device__ int   g_rowptr[N_NODES + 1];
__device__ int   g_cursor[N_NODES];
__device__ int   g_col[N_EDGES];          // CSR-by-dst: source node ids
__device__ float g_dinv[N_NODES];
__device__ float g_p[N_NODES * 48];       // buffer 0 (max F = 48)
__device__ float g_agg[N_NODES * 48];     // buffer 1 (max F = 48)
__device__ float g_h[N_NODES * 64];       // buffer 2 (max F = 64)
__device__ float g_bnsum[64];
__device__ float g_bnsq[64];
__device__ float g_bna[64];
__device__ float g_bnc[64];

// compile-time scratch-buffer selector — avoids passing __device__ symbols
// through host-side kernel arguments (illegal generic pointers).
template<int B> __device__ __forceinline__ float* buf() {
    if (B == 0) return g_p;
    if (B == 1) return g_agg;
    return g_h;
}

// ---------------- init: zero counts + BN accumulators ----------------
__global__ void k_init() {
    int idx = blockIdx.x * blockDim.x + threadIdx.x;
    int stride = gridDim.x * blockDim.x;
    for (int i = idx; i < N_NODES; i += stride) g_count[i] = 0;
    if (idx < 64) { g_bnsum[idx] = 0.f; g_bnsq[idx] = 0.f; }
}

// ---------------- degree histogram (edge_index is int32!) ----------------
__global__ void k_count(const int* __restrict__ ei) {
    int e = blockIdx.x * blockDim.x + threadIdx.x;
    if (e < N_EDGES) {
        int dst = ei[N_EDGES + e];
        atomicAdd(&g_count[dst], 1);
    }
}

// ---------------- single-block exclusive scan (rowptr + cursor) ----------------
__global__ void k_scan() {
    __shared__ int wsum[32];
    __shared__ int carry_s;
    const int tid = threadIdx.x;            // 1024 threads
    const int lane = tid & 31, wid = tid >> 5;
    if (tid == 0) carry_s = 0;
    __syncthreads();
    for (int base = 0; base < N_NODES; base += 1024) {
        int i = base + tid;
        int v = (i < N_NODES) ? g_count[i] : 0;
        int x = v;
        #pragma unroll
        for (int s = 1; s < 32; s <<= 1) {
            int y = __shfl_up_sync(0xffffffffu, x, s);
            if (lane >= s) x += y;
        }
        if (lane == 31) wsum[wid] = x;
        __syncthreads();
        if (wid == 0) {
            int w = wsum[lane];
            #pragma unroll
            for (int s = 1; s < 32; s <<= 1) {
                int y = __shfl_up_sync(0xffffffffu, w, s);
                if (lane >= s) w += y;
            }
            wsum[lane] = w;                 // inclusive scan of warp totals
        }
        __syncthreads();
        int carry = carry_s;
        int excl = carry + (wid > 0 ? wsum[wid - 1] : 0) + (x - v);
        if (i < N_NODES) { g_rowptr[i] = excl; g_cursor[i] = excl; }
        __syncthreads();
        if (tid == 0) carry_s = carry + wsum[31];
        __syncthreads();
    }
    if (tid == 0) g_rowptr[N_NODES] = carry_s;   // == N_EDGES
}

// ---------------- dinv = rsqrt(deg + 1) ----------------
__global__ void k_dinv() {
    int i = blockIdx.x * blockDim.x + threadIdx.x;
    if (i < N_NODES) g_dinv[i] = rsqrtf((float)g_count[i] + 1.0f);
}

// ---------------- CSR scatter (edge_index is int32) ----------------
__global__ void k_scatter(const int* __restrict__ ei) {
    int e = blockIdx.x * blockDim.x + threadIdx.x;
    if (e < N_EDGES) {
        int src = ei[e];
        int dst = ei[N_EDGES + e];
        int pos = atomicAdd(&g_cursor[dst], 1);
        g_col[pos] = src;
    }
}

// ---------------- p (buf0) = dinv .* x  (F = 20) ----------------
__global__ void k_scale20(const float* __restrict__ x) {
    int idx = blockIdx.x * blockDim.x + threadIdx.x;
    int total = N_NODES * 20;
    if (idx < total) {
        int node = idx / 20;
        g_p[idx] = x[idx] * g_dinv[node];
    }
}

// ---------------- gather-aggregate: out[i] = dinv[i]*(p[i] + sum_{src->i} p[src]) ----
template<int F, int PB, int OB>
__global__ void k_gather() {
    const float* __restrict__ p = buf<PB>();
    float* __restrict__ out = buf<OB>();
    const int lane = threadIdx.x & 31;
    int warp = (blockIdx.x * blockDim.x + threadIdx.x) >> 5;
    const int nwarps = (gridDim.x * blockDim.x) >> 5;
    constexpr int F2 = (F > 32) ? (F - 32) : 0;
    const bool v0 = (lane < ((F < 32) ? F : 32));
    const bool v1 = F2 && (lane < F2);
    for (int i = warp; i < N_NODES; i += nwarps) {
        const int beg = g_rowptr[i];
        const int end = g_rowptr[i + 1];
        float acc0 = 0.f, acc1 = 0.f;
        if (v0) acc0 = p[i * F + lane];            // self-loop term
        if (v1) acc1 = p[i * F + 32 + lane];
        for (int jb = beg; jb < end; jb += 32) {
            int j = jb + lane;
            int c = (j < end) ? g_col[j] : 0;
            int cnt = min(32, end - jb);
            for (int k = 0; k < cnt; k++) {
                int s = __shfl_sync(0xffffffffu, c, k);
                int sb = s * F;
                if (v0) acc0 += p[sb + lane];
                if (v1) acc1 += p[sb + 32 + lane];
            }
        }
        float d = g_dinv[i];
        if (v0) out[i * F + lane] = d * acc0;
        if (v1) out[i * F + 32 + lane] = d * acc1;
    }
}

// ---------------- GEMM: out[n,:] = f(in[n,:]) @ W, f = optional BN-affine+ReLU ----
// Each thread computes 2 output features via fma.rn.f32x2. Inputs staged in
// shared memory duplicated as (v,v) so one LDS.64 feeds the packed FMA.
template<int FIN, int FOUT, int NPB, bool BN_IN, bool DINV_OUT, int IB, int OB>
__global__ void k_gemm(const float* __restrict__ W) {
    const float* __restrict__ in = buf<IB>();
    float* __restrict__ out = buf<OB>();
    constexpr int PAIRS = FOUT / 2;
    __shared__ float2 sW[FIN * PAIRS];
    __shared__ float2 sIn[NPB * FIN];
    const int tid = threadIdx.x;
    const int nthreads = NPB * PAIRS;     // == blockDim.x
    for (int idx = tid; idx < FIN * PAIRS; idx += nthreads) {
        int k = idx / PAIRS, pr = idx - k * PAIRS;
        sW[idx] = make_float2(W[k * FOUT + 2 * pr], W[k * FOUT + 2 * pr + 1]);
    }
    const int grp = tid / PAIRS;
    const int pr  = tid - grp * PAIRS;
    for (int base = blockIdx.x * NPB; base < N_NODES; base += gridDim.x * NPB) {
        __syncthreads();
        for (int idx = tid; idx < NPB * FIN; idx += nthreads) {
            int nl = idx / FIN, k = idx - nl * FIN;
            int node = base + nl;
            float v = 0.f;
            if (node < N_NODES) {
                v = in[node * FIN + k];
                if (BN_IN) v = fmaxf(fmaf(v, g_bna[k], g_bnc[k]), 0.f);
            }
            sIn[idx] = make_float2(v, v);
        }
        __syncthreads();
        int node = base + grp;
        if (node < N_NODES) {
            unsigned long long a0 = 0ULL, a1 = 0ULL;
            #pragma unroll
            for (int k = 0; k < FIN; k += 2) {
                unsigned long long i0 =
                    *reinterpret_cast<const unsigned long long*>(&sIn[grp * FIN + k]);
                unsigned long long w0 =
                    *reinterpret_cast<const unsigned long long*>(&sW[k * PAIRS + pr]);
                asm("fma.rn.f32x2 %0, %1, %2, %0;" : "+l"(a0) : "l"(i0), "l"(w0));
                unsigned long long i1 =
                    *reinterpret_cast<const unsigned long long*>(&sIn[grp * FIN + k + 1]);
                unsigned long long w1 =
                    *reinterpret_cast<const unsigned long long*>(&sW[(k + 1) * PAIRS + pr]);
                asm("fma.rn.f32x2 %0, %1, %2, %0;" : "+l"(a1) : "l"(i1), "l"(w1));
            }
            unsigned long long a;
            asm("add.rn.f32x2 %0, %1, %2;" : "=l"(a) : "l"(a0), "l"(a1));
            float2 o = *reinterpret_cast<float2*>(&a);
            if (DINV_OUT) { float d = g_dinv[node]; o.x *= d; o.y *= d; }
            *reinterpret_cast<float2*>(&out[node * FOUT + 2 * pr]) = o;
        }
    }
}

// ---------------- per-feature sum / sumsq (blockDim must be multiple of F) ----
template<int F, int IB>
__global__ void k_stats() {
    const float* __restrict__ x = buf<IB>();
    __shared__ float ssum[F];
    __shared__ float ssq[F];
    const int tid = threadIdx.x;
    for (int i = tid; i < F; i += blockDim.x) { ssum[i] = 0.f; ssq[i] = 0.f; }
    __syncthreads();
    float s = 0.f, q = 0.f;
    const int total = N_NODES * F;
    const int stride = gridDim.x * blockDim.x;  // multiple of F
    for (int idx = blockIdx.x * blockDim.x + tid; idx < total; idx += stride) {
        float v = x[idx];
        s += v; q += v * v;
    }
    int f = tid % F;
    atomicAdd(&ssum[f], s);
    atomicAdd(&ssq[f], q);
    __syncthreads();
    for (int i = tid; i < F; i += blockDim.x) {
        atomicAdd(&g_bnsum[i], ssum[i]);
        atomicAdd(&g_bnsq[i], ssq[i]);
    }
}

// ---------------- BN params: a = g*rsqrt(var+eps), c = beta - mu*a; re-zero sums ----
template<int F>
__global__ void k_bnparam(const float* __restrict__ g, const float* __restrict__ beta) {
    int f = threadIdx.x;
    if (f < F) {
        float inv_n = 1.0f / (float)N_NODES;
        float mu  = g_bnsum[f] * inv_n;
        float var = g_bnsq[f] * inv_n - mu * mu;
        float a = g[f] * rsqrtf(var + BN_EPS);
        g_bna[f] = a;
        g_bnc[f] = beta[f] - mu * a;
        g_bnsum[f] = 0.f;
        g_bnsq[f]  = 0.f;
    }
}

// ---------------- final apply (no ReLU): out = bn(g_h) ----------------
__global__ void k_apply(float* __restrict__ out) {
    int idx = blockIdx.x * blockDim.x + threadIdx.x;
    const int total = N_NODES * 32;
    if (idx < total) {
        int f = idx & 31;
        out[idx] = fmaf(g_h[idx], g_bna[f], g_bnc[f]);
    }
}

// ---------------- launcher ----------------
extern "C" void kernel_launch(void* const* d_in, const int* in_sizes, int n_in,
                              void* d_out, int out_size) {
    const float* x   = (const float*)d_in[0];
    const int*   ei  = (const int*)d_in[1];          // int32 (JAX x64 disabled)
    const float* W1  = (const float*)d_in[2];
    const float* g1  = (const float*)d_in[4];
    const float* be1 = (const float*)d_in[5];
    const float* W2  = (const float*)d_in[6];
    const float* g2  = (const float*)d_in[8];
    const float* be2 = (const float*)d_in[9];
    const float* W3  = (const float*)d_in[10];
    const float* g3  = (const float*)d_in[12];
    const float* be3 = (const float*)d_in[13];
    float* out = (float*)d_out;

    const int EB = (N_EDGES + 255) / 256;          // 6250

    // ---- graph normalization + CSR build ----
    k_init<<<512, 256>>>();
    k_count<<<EB, 256>>>(ei);
    k_scan<<<1, 1024>>>();
    k_dinv<<<(N_NODES + 255) / 256, 256>>>();
    k_scatter<<<EB, 256>>>(ei);

    // ---- layer 1: scatter-first (F=20), then GEMM 20->64, BN stats ----
    k_scale20<<<(N_NODES * 20 + 255) / 256, 256>>>(x);
    k_gather<20, 0, 1><<<12500, 256>>>();                 // g_p -> g_agg
    k_gemm<20, 64, 8, false, false, 1, 2><<<12500, 256>>>(W1);   // g_agg -> g_h
    k_stats<64, 2><<<512, 256>>>();
    k_bnparam<64><<<1, 64>>>(g1, be1);

    // ---- layer 2: GEMM 64->48 (BN1+ReLU on input, dinv on output), gather ----
    k_gemm<64, 48, 8, true, true, 2, 0><<<12500, 192>>>(W2);     // g_h -> g_p
    k_gather<48, 0, 1><<<12500, 256>>>();                 // g_p -> g_agg
    k_stats<48, 1><<<512, 192>>>();
    k_bnparam<48><<<1, 64>>>(g2, be2);

    // ---- layer 3: GEMM 48->32 (BN2+ReLU on input, dinv on output), gather ----
    k_gemm<48, 32, 16, true, true, 1, 0><<<6250, 256>>>(W3);     // g_agg -> g_p
    k_gather<32, 0, 2><<<12500, 256>>>();                 // g_p -> g_h
    k_stats<32, 2><<<512, 256>>>();
    k_bnparam<32><<<1, 64>>>(g3, be3);

    // ---- final BN apply ----
    k_apply<<<(N_NODES * 32 + 255) / 256, 256>>>(out);
}

// round 4
// speedup vs baseline: 1.1851x; 1.1851x over previous
#include <cuda_runtime.h>
#include <cstdint>

#define N_NODES 100000
#define N_EDGES 1600000
#define BN_EPS  1e-5f
#define NB_SCAN 391   // ceil(N_NODES/256)

// ---------------- scratch (static __device__, no allocations) ----------------
__device__ int   g_count[N_NODES];
__device__ int   g_rowptr[N_NODES + 1];
__device__ int   g_cursor[N_NODES];
__device__ int   g_col[N_EDGES];          // CSR-by-dst: source node ids
__device__ int   g_bsum[NB_SCAN];
__device__ int   g_boff[NB_SCAN];
__device__ float g_dinv[N_NODES];
__device__ float g_p[N_NODES * 48];       // buffer 0 (max F = 48)
__device__ float g_agg[N_NODES * 48];     // buffer 1 (max F = 48)
__device__ float g_h[N_NODES * 64];       // buffer 2 (max F = 64)
__device__ float g_bnsum[64];
__device__ float g_bnsq[64];
__device__ float g_bna[64];
__device__ float g_bnc[64];

template<int B> __device__ __forceinline__ float* buf() {
    if (B == 0) return g_p;
    if (B == 1) return g_agg;
    return g_h;
}

// ---------------- init: zero counts + BN accumulators ----------------
__global__ void k_init() {
    int idx = blockIdx.x * blockDim.x + threadIdx.x;
    int stride = gridDim.x * blockDim.x;
    for (int i = idx; i < N_NODES; i += stride) g_count[i] = 0;
    if (idx < 64) { g_bnsum[idx] = 0.f; g_bnsq[idx] = 0.f; }
}

// ---------------- degree histogram (edge_index is int32) ----------------
__global__ void k_count(const int* __restrict__ ei) {
    int e = blockIdx.x * blockDim.x + threadIdx.x;
    if (e < N_EDGES) atomicAdd(&g_count[ei[N_EDGES + e]], 1);
}

// ---------------- hierarchical scan: pass A (per-block sums) ----------------
__global__ void k_scanA() {
    const int tid = threadIdx.x, lane = tid & 31, wid = tid >> 5;
    int i = blockIdx.x * 256 + tid;
    int v = (i < N_NODES) ? g_count[i] : 0;
    #pragma unroll
    for (int s = 16; s > 0; s >>= 1) v += __shfl_down_sync(0xffffffffu, v, s);
    __shared__ int ws[8];
    if (lane == 0) ws[wid] = v;
    __syncthreads();
    if (tid == 0) {
        int t = 0;
        #pragma unroll
        for (int w = 0; w < 8; w++) t += ws[w];
        g_bsum[blockIdx.x] = t;
    }
}

// ---------------- pass B: 1-block exclusive scan of NB_SCAN partials ----------
__global__ void k_scanB() {
    const int tid = threadIdx.x;           // 512 threads
    const int lane = tid & 31, wid = tid >> 5;
    int v = (tid < NB_SCAN) ? g_bsum[tid] : 0;
    int x = v;
    #pragma unroll
    for (int s = 1; s < 32; s <<= 1) {
        int y = __shfl_up_sync(0xffffffffu, x, s);
        if (lane >= s) x += y;
    }
    __shared__ int ws[16];
    if (lane == 31) ws[wid] = x;
    __syncthreads();
    if (wid == 0 && lane < 16) {
        int w = ws[lane];
        #pragma unroll
        for (int s = 1; s < 16; s <<= 1) {
            int y = __shfl_up_sync(0x0000ffffu, w, s);
            if (lane >= s) w += y;
        }
        ws[lane] = w;
    }
    __syncthreads();
    int excl = (wid > 0 ? ws[wid - 1] : 0) + (x - v);
    if (tid < NB_SCAN) g_boff[tid] = excl;
}

// ---------------- pass C: block-local scan + offsets; rowptr/cursor/dinv ----
__global__ void k_scanC() {
    const int tid = threadIdx.x, lane = tid & 31, wid = tid >> 5;
    int i = blockIdx.x * 256 + tid;
    int v = (i < N_NODES) ? g_count[i] : 0;
    int x = v;
    #pragma unroll
    for (int s = 1; s < 32; s <<= 1) {
        int y = __shfl_up_sync(0xffffffffu, x, s);
        if (lane >= s) x += y;
    }
    __shared__ int ws[8];
    if (lane == 31) ws[wid] = x;
    __syncthreads();
    if (wid == 0 && lane < 8) {
        int w = ws[lane];
        #pragma unroll
        for (int s = 1; s < 8; s <<= 1) {
            int y = __shfl_up_sync(0x000000ffu, w, s);
            if (lane >= s) w += y;
        }
        ws[lane] = w;
    }
    __syncthreads();
    int excl = g_boff[blockIdx.x] + (wid > 0 ? ws[wid - 1] : 0) + (x - v);
    if (i < N_NODES) {
        g_rowptr[i] = excl;
        g_cursor[i] = excl;
        g_dinv[i]   = rsqrtf((float)v + 1.0f);
    }
    if (i == 0) g_rowptr[N_NODES] = N_EDGES;
}

// ---------------- CSR scatter ----------------
__global__ void k_scatter(const int* __restrict__ ei) {
    int e = blockIdx.x * blockDim.x + threadIdx.x;
    if (e < N_EDGES) {
        int src = ei[e];
        int dst = ei[N_EDGES + e];
        int pos = atomicAdd(&g_cursor[dst], 1);
        g_col[pos] = src;
    }
}

// ---------------- p (buf0) = dinv .* x  (F = 20) ----------------
__global__ void k_scale20(const float* __restrict__ x) {
    int idx = blockIdx.x * blockDim.x + threadIdx.x;
    int total = N_NODES * 20;
    if (idx < total) {
        int node = idx / 20;
        g_p[idx] = x[idx] * g_dinv[node];
    }
}

// ------- gather-aggregate: out[i] = dinv[i]*(p[i] + sum_{src->i} p[src]) -----
// Optional fused BN statistics of the written output (features = lane / 32+lane).
template<int F, int PB, int OB, bool STATS>
__global__ void k_gather() {
    const float* __restrict__ p = buf<PB>();
    float* __restrict__ out = buf<OB>();
    __shared__ float bsum[STATS ? F : 1];
    __shared__ float bsq[STATS ? F : 1];
    const int tid = threadIdx.x;
    const int lane = tid & 31;
    if (STATS) {
        for (int i = tid; i < F; i += blockDim.x) { bsum[i] = 0.f; bsq[i] = 0.f; }
        __syncthreads();
    }
    int warp = (blockIdx.x * blockDim.x + tid) >> 5;
    const int nwarps = (gridDim.x * blockDim.x) >> 5;
    constexpr int F2 = (F > 32) ? (F - 32) : 0;
    const bool v0 = (lane < ((F < 32) ? F : 32));
    const bool v1 = F2 && (lane < F2);
    float s0 = 0.f, q0 = 0.f, s1 = 0.f, q1 = 0.f;
    for (int i = warp; i < N_NODES; i += nwarps) {
        const int beg = g_rowptr[i];
        const int end = g_rowptr[i + 1];
        float acc0 = 0.f, acc1 = 0.f;
        if (v0) acc0 = p[i * F + lane];            // self-loop term
        if (v1) acc1 = p[i * F + 32 + lane];
        int jb = beg;
        for (; jb + 32 <= end; jb += 32) {         // full chunks: unrolled
            int c = g_col[jb + lane];
            #pragma unroll
            for (int k = 0; k < 32; k++) {
                int sb = __shfl_sync(0xffffffffu, c, k) * F;
                if (v0) acc0 += p[sb + lane];
                if (v1) acc1 += p[sb + 32 + lane];
            }
        }
        if (jb < end) {                            // remainder
            int j = jb + lane;
            int c = (j < end) ? g_col[j] : 0;
            int cnt = end - jb;
            for (int k = 0; k < cnt; k++) {
                int sb = __shfl_sync(0xffffffffu, c, k) * F;
                if (v0) acc0 += p[sb + lane];
                if (v1) acc1 += p[sb + 32 + lane];
            }
        }
        float d = g_dinv[i];
        if (v0) {
            float o = d * acc0;
            out[i * F + lane] = o;
            if (STATS) { s0 += o; q0 += o * o; }
        }
        if (v1) {
            float o = d * acc1;
            out[i * F + 32 + lane] = o;
            if (STATS) { s1 += o; q1 += o * o; }
        }
    }
    if (STATS) {
        if (v0) { atomicAdd(&bsum[lane], s0); atomicAdd(&bsq[lane], q0); }
        if (v1) { atomicAdd(&bsum[32 + lane], s1); atomicAdd(&bsq[32 + lane], q1); }
        __syncthreads();
        for (int i = tid; i < F; i += blockDim.x) {
            atomicAdd(&g_bnsum[i], bsum[i]);
            atomicAdd(&g_bnsq[i], bsq[i]);
        }
    }
}

// ---------------- GEMM: out[n,:] = f(in[n,:]) @ W  (f = BN-affine+ReLU) ------
// fma.rn.f32x2 packed math; optional fused BN stats of the outputs.
template<int FIN, int FOUT, int NPB, bool BN_IN, bool DINV_OUT, int IB, int OB, bool STATS>
__global__ void k_gemm(const float* __restrict__ W) {
    const float* __restrict__ in = buf<IB>();
    float* __restrict__ out = buf<OB>();
    constexpr int PAIRS = FOUT / 2;
    __shared__ float2 sW[FIN * PAIRS];
    __shared__ float2 sIn[NPB * FIN];
    __shared__ float bsum[STATS ? FOUT : 1];
    __shared__ float bsq[STATS ? FOUT : 1];
    const int tid = threadIdx.x;
    const int nthreads = NPB * PAIRS;     // == blockDim.x
    for (int idx = tid; idx < FIN * PAIRS; idx += nthreads) {
        int k = idx / PAIRS, pr = idx - k * PAIRS;
        sW[idx] = make_float2(W[k * FOUT + 2 * pr], W[k * FOUT + 2 * pr + 1]);
    }
    if (STATS) {
        for (int i = tid; i < FOUT; i += nthreads) { bsum[i] = 0.f; bsq[i] = 0.f; }
    }
    const int grp = tid / PAIRS;
    const int pr  = tid - grp * PAIRS;
    float s0 = 0.f, q0 = 0.f, s1 = 0.f, q1 = 0.f;
    for (int base = blockIdx.x * NPB; base < N_NODES; base += gridDim.x * NPB) {
        __syncthreads();
        for (int idx = tid; idx < NPB * FIN; idx += nthreads) {
            int nl = idx / FIN, k = idx - nl * FIN;
            int node = base + nl;
            float v = 0.f;
            if (node < N_NODES) {
                v = in[node * FIN + k];
                if (BN_IN) v = fmaxf(fmaf(v, g_bna[k], g_bnc[k]), 0.f);
            }
            sIn[idx] = make_float2(v, v);
        }
        __syncthreads();
        int node = base + grp;
        if (node < N_NODES) {
            unsigned long long a0 = 0ULL, a1 = 0ULL;
            #pragma unroll
            for (int k = 0; k < FIN; k += 2) {
                unsigned long long i0 =
                    *reinterpret_cast<const unsigned long long*>(&sIn[grp * FIN + k]);
                unsigned long long w0 =
                    *reinterpret_cast<const unsigned long long*>(&sW[k * PAIRS + pr]);
                asm("fma.rn.f32x2 %0, %1, %2, %0;" : "+l"(a0) : "l"(i0), "l"(w0));
                unsigned long long i1 =
                    *reinterpret_cast<const unsigned long long*>(&sIn[grp * FIN + k + 1]);
                unsigned long long w1 =
                    *reinterpret_cast<const unsigned long long*>(&sW[(k + 1) * PAIRS + pr]);
                asm("fma.rn.f32x2 %0, %1, %2, %0;" : "+l"(a1) : "l"(i1), "l"(w1));
            }
            unsigned long long a;
            asm("add.rn.f32x2 %0, %1, %2;" : "=l"(a) : "l"(a0), "l"(a1));
            float2 o = *reinterpret_cast<float2*>(&a);
            if (DINV_OUT) { float d = g_dinv[node]; o.x *= d; o.y *= d; }
            *reinterpret_cast<float2*>(&out[node * FOUT + 2 * pr]) = o;
            if (STATS) { s0 += o.x; q0 += o.x * o.x; s1 += o.y; q1 += o.y * o.y; }
        }
    }
    if (STATS) {
        atomicAdd(&bsum[2 * pr],     s0); atomicAdd(&bsq[2 * pr],     q0);
        atomicAdd(&bsum[2 * pr + 1], s1); atomicAdd(&bsq[2 * pr + 1], q1);
        __syncthreads();
        for (int i = tid; i < FOUT; i += nthreads) {
            atomicAdd(&g_bnsum[i], bsum[i]);
            atomicAdd(&g_bnsq[i], bsq[i]);
        }
    }
}

// ---------------- BN params: a = g*rsqrt(var+eps), c = beta - mu*a ----------
template<int F>
__global__ void k_bnparam(const float* __restrict__ g, const float* __restrict__ beta) {
    int f = threadIdx.x;
    if (f < F) {
        float inv_n = 1.0f / (float)N_NODES;
        float mu  = g_bnsum[f] * inv_n;
        float var = g_bnsq[f] * inv_n - mu * mu;
        float a = g[f] * rsqrtf(var + BN_EPS);
        g_bna[f] = a;
        g_bnc[f] = beta[f] - mu * a;
        g_bnsum[f] = 0.f;
        g_bnsq[f]  = 0.f;
    }
}

// ---------------- final apply (no ReLU): out = bn(g_h) ----------------
__global__ void k_apply(float* __restrict__ out) {
    int idx = blockIdx.x * blockDim.x + threadIdx.x;
    const int total = N_NODES * 32;
    if (idx < total) {
        int f = idx & 31;
        out[idx] = fmaf(g_h[idx], g_bna[f], g_bnc[f]);
    }
}

// ---------------- launcher ----------------
extern "C" void kernel_launch(void* const* d_in, const int* in_sizes, int n_in,
                              void* d_out, int out_size) {
    const float* x   = (const float*)d_in[0];
    const int*   ei  = (const int*)d_in[1];          // int32
    const float* W1  = (const float*)d_in[2];
    const float* g1  = (const float*)d_in[4];
    const float* be1 = (const float*)d_in[5];
    const float* W2  = (const float*)d_in[6];
    const float* g2  = (const float*)d_in[8];
    const float* be2 = (const float*)d_in[9];
    const float* W3  = (const float*)d_in[10];
    const float* g3  = (const float*)d_in[12];
    const float* be3 = (const float*)d_in[13];
    float* out = (float*)d_out;

    const int EB = (N_EDGES + 255) / 256;          // 6250

    // ---- graph normalization + CSR build (hierarchical scan) ----
    k_init<<<512, 256>>>();
    k_count<<<EB, 256>>>(ei);
    k_scanA<<<NB_SCAN, 256>>>();
    k_scanB<<<1, 512>>>();
    k_scanC<<<NB_SCAN, 256>>>();
    k_scatter<<<EB, 256>>>(ei);

    // ---- layer 1: scatter-first (F=20), GEMM 20->64 (+BN1 stats) ----
    k_scale20<<<(N_NODES * 20 + 255) / 256, 256>>>(x);
    k_gather<20, 0, 1, false><<<2048, 256>>>();                    // g_p -> g_agg
    k_gemm<20, 64, 8, false, false, 1, 2, true><<<2048, 256>>>(W1); // g_agg -> g_h
    k_bnparam<64><<<1, 64>>>(g1, be1);

    // ---- layer 2: GEMM 64->48 (BN1+ReLU in, dinv out), gather (+BN2 stats) ----
    k_gemm<64, 48, 8, true, true, 2, 0, false><<<12500, 192>>>(W2); // g_h -> g_p
    k_gather<48, 0, 1, true><<<2048, 256>>>();                      // g_p -> g_agg
    k_bnparam<48><<<1, 64>>>(g2, be2);

    // ---- layer 3: GEMM 48->32 (BN2+ReLU in, dinv out), gather (+BN3 stats) ----
    k_gemm<48, 32, 16, true, true, 1, 0, false><<<6250, 256>>>(W3); // g_agg -> g_p
    k_gather<32, 0, 2, true><<<2048, 256>>>();                      // g_p -> g_h
    k_bnparam<32><<<1, 64>>>(g3, be3);

    // ---- final BN apply ----
    k_apply<<<(N_NODES * 32 + 255) / 256, 256>>>(out);
}

// round 5
// speedup vs baseline: 1.3866x; 1.1700x over previous
#include <cuda_runtime.h>
#include <cstdint>

#define N_NODES 100000
#define N_EDGES 1600000
#define BN_EPS  1e-5f
#define NB_SCAN 391   // ceil(N_NODES/256)

// ---------------- scratch (static __device__, no allocations) ----------------
__device__ int    g_count[N_NODES];
__device__ int    g_rowptr[N_NODES + 1];
__device__ int    g_cursor[N_NODES];
__device__ int    g_col[N_EDGES];           // CSR-by-dst: source node ids
__device__ unsigned int g_state[NB_SCAN];   // lookback scan states
__device__ float  g_dinv[N_NODES];
__device__ float4 g_b0[N_NODES * 12];       // buffer 0 (48 floats/row max)
__device__ float4 g_b1[N_NODES * 12];       // buffer 1 (48 floats/row max)
__device__ float4 g_b2[N_NODES * 16];       // buffer 2 (64 floats/row max)
__device__ float  g_bnsum[64];
__device__ float  g_bnsq[64];
__device__ float  g_bna[64];
__device__ float  g_bnc[64];

template<int B> __device__ __forceinline__ float4* buf4() {
    if (B == 0) return g_b0;
    if (B == 1) return g_b1;
    return g_b2;
}
template<int B> __device__ __forceinline__ float* buff() {
    return (float*)buf4<B>();
}

// ---------------- init: zero counts + scan states + BN accumulators ----------
__global__ void k_init() {
    int idx = blockIdx.x * blockDim.x + threadIdx.x;
    int stride = gridDim.x * blockDim.x;
    for (int i = idx; i < N_NODES; i += stride) g_count[i] = 0;
    if (idx < NB_SCAN) g_state[idx] = 0u;
    if (idx < 64) { g_bnsum[idx] = 0.f; g_bnsq[idx] = 0.f; }
}

// ---------------- degree histogram (int4-vectorized edge loads) -------------
__global__ void k_count(const int* __restrict__ ei) {
    int t = blockIdx.x * blockDim.x + threadIdx.x;
    if (t < N_EDGES / 4) {
        int4 d = reinterpret_cast<const int4*>(ei + N_EDGES)[t];
        atomicAdd(&g_count[d.x], 1);
        atomicAdd(&g_count[d.y], 1);
        atomicAdd(&g_count[d.z], 1);
        atomicAdd(&g_count[d.w], 1);
    }
}

// ------- single-kernel decoupled-lookback scan: rowptr + cursor + dinv ------
__global__ void k_scan() {
    const int tid = threadIdx.x, lane = tid & 31, wid = tid >> 5;
    const int bid = blockIdx.x;
    int i = bid * 256 + tid;
    int v = (i < N_NODES) ? g_count[i] : 0;
    // warp inclusive scan
    int x = v;
    #pragma unroll
    for (int s = 1; s < 32; s <<= 1) {
        int y = __shfl_up_sync(0xffffffffu, x, s);
        if (lane >= s) x += y;
    }
    __shared__ int ws[8];
    __shared__ unsigned int s_prefix;
    if (lane == 31) ws[wid] = x;
    __syncthreads();
    if (wid == 0) {
        // scan the 8 warp totals; publish block aggregate; lookback
        int wv = (lane < 8) ? ws[lane] : 0;
        int sc = wv;
        #pragma unroll
        for (int s = 1; s < 8; s <<= 1) {
            int y = __shfl_up_sync(0xffffffffu, sc, s);
            if (lane >= s) sc += y;
        }
        int tot = __shfl_sync(0xffffffffu, sc, 7);
        if (lane == 0) atomicExch(&g_state[bid], (1u << 25) | (unsigned)tot);
        if (lane < 8) ws[lane] = sc;          // inclusive warp-sums
        // warp-parallel lookback over published aggregates
        unsigned run = 0;
        for (int basej = bid - 1; basej >= 0; basej -= 32) {
            int j = basej - lane;
            unsigned st;
            do {
                st = (j >= 0) ? *(volatile unsigned int*)&g_state[j] : (1u << 25);
            } while (__any_sync(0xffffffffu, st < (1u << 25)));
            if (j >= 0) run += st & 0x01FFFFFFu;
        }
        #pragma unroll
        for (int s = 16; s > 0; s >>= 1) run += __shfl_down_sync(0xffffffffu, run, s);
        if (lane == 0) s_prefix = run;
    }
    __syncthreads();
    int excl = (int)s_prefix + (wid > 0 ? ws[wid - 1] : 0) + (x - v);
    if (i < N_NODES) {
        g_rowptr[i] = excl;
        g_cursor[i] = excl;
        g_dinv[i]   = rsqrtf((float)v + 1.0f);
    }
    if (i == 0) g_rowptr[N_NODES] = N_EDGES;
}

// ---------------- CSR scatter (profiled: launch index 3) ----------------
__global__ void k_scatter(const int* __restrict__ ei) {
    int e = blockIdx.x * blockDim.x + threadIdx.x;
    if (e < N_EDGES) {
        int src = ei[e];
        int dst = ei[N_EDGES + e];
        int pos = atomicAdd(&g_cursor[dst], 1);
        g_col[pos] = src;
    }
}

// ------- b0 rows (stride 32) = dinv .* x (first 20 cols), zeros 20..31 ------
__global__ void k_scalepad(const float* __restrict__ x) {
    int idx = blockIdx.x * blockDim.x + threadIdx.x;
    const int total = N_NODES * 32;
    if (idx < total) {
        int node = idx >> 5, c = idx & 31;
        float v = 0.f;
        if (c < 20) v = x[node * 20 + c] * g_dinv[node];
        ((float*)g_b0)[idx] = v;
    }
}

// ------- gather-aggregate (float4 rows): out[i]=dinv[i]*(p[i]+sum p[src]) ---
// FPAD: padded row width in floats (32 or 48). LW = FPAD/4 lanes per edge,
// EPW edges processed per warp-iteration.
template<int FPAD, int EPW, int PB, int OB, bool STATS>
__global__ void k_gather() {
    constexpr int LW = FPAD / 4;
    const float4* __restrict__ p4 = buf4<PB>();
    float4* __restrict__ o4 = buf4<OB>();
    __shared__ float bsum[STATS ? FPAD : 1];
    __shared__ float bsq[STATS ? FPAD : 1];
    const int tid = threadIdx.x;
    const int lane = tid & 31;
    const int grp = lane / LW;         // edge slot
    const int c   = lane % LW;         // float4 chunk within row
    const bool active = grp < EPW;
    if (STATS) {
        for (int i = tid; i < FPAD; i += blockDim.x) { bsum[i] = 0.f; bsq[i] = 0.f; }
        __syncthreads();
    }
    int warp = (blockIdx.x * blockDim.x + tid) >> 5;
    const int nwarps = (gridDim.x * blockDim.x) >> 5;
    float4 s4 = {0.f, 0.f, 0.f, 0.f}, q4 = {0.f, 0.f, 0.f, 0.f};
    for (int i = warp; i < N_NODES; i += nwarps) {
        const int beg = g_rowptr[i];
        const int end = g_rowptr[i + 1];
        float4 acc = {0.f, 0.f, 0.f, 0.f};
        if (grp == 0) acc = p4[(size_t)i * LW + c];      // self-loop row
        for (int jb = beg; jb < end; jb += EPW) {
            int e = jb + grp;
            bool val = active && (e < end);
            if (val) {
                int idx = g_col[e];
                float4 v = p4[(size_t)idx * LW + c];
                acc.x += v.x; acc.y += v.y; acc.z += v.z; acc.w += v.w;
            }
        }
        // reduce across edge slots
        if (LW == 8) {               // EPW=4: xor-tree
            acc.x += __shfl_xor_sync(0xffffffffu, acc.x, 8);
            acc.y += __shfl_xor_sync(0xffffffffu, acc.y, 8);
            acc.z += __shfl_xor_sync(0xffffffffu, acc.z, 8);
            acc.w += __shfl_xor_sync(0xffffffffu, acc.w, 8);
            acc.x += __shfl_xor_sync(0xffffffffu, acc.x, 16);
            acc.y += __shfl_xor_sync(0xffffffffu, acc.y, 16);
            acc.z += __shfl_xor_sync(0xffffffffu, acc.z, 16);
            acc.w += __shfl_xor_sync(0xffffffffu, acc.w, 16);
        } else {                     // LW=12, EPW=2: one down-12 step
            float tx = __shfl_down_sync(0xffffffffu, acc.x, 12);
            float ty = __shfl_down_sync(0xffffffffu, acc.y, 12);
            float tz = __shfl_down_sync(0xffffffffu, acc.z, 12);
            float tw = __shfl_down_sync(0xffffffffu, acc.w, 12);
            acc.x += tx; acc.y += ty; acc.z += tz; acc.w += tw;
        }
        if (grp == 0) {
            float d = g_dinv[i];
            float4 o = {d * acc.x, d * acc.y, d * acc.z, d * acc.w};
            o4[(size_t)i * LW + c] = o;
            if (STATS) {
                s4.x += o.x; s4.y += o.y; s4.z += o.z; s4.w += o.w;
                q4.x += o.x * o.x; q4.y += o.y * o.y;
                q4.z += o.z * o.z; q4.w += o.w * o.w;
            }
        }
    }
    if (STATS) {
        if (grp == 0) {
            atomicAdd(&bsum[c * 4 + 0], s4.x); atomicAdd(&bsq[c * 4 + 0], q4.x);
            atomicAdd(&bsum[c * 4 + 1], s4.y); atomicAdd(&bsq[c * 4 + 1], q4.y);
            atomicAdd(&bsum[c * 4 + 2], s4.z); atomicAdd(&bsq[c * 4 + 2], q4.z);
            atomicAdd(&bsum[c * 4 + 3], s4.w); atomicAdd(&bsq[c * 4 + 3], q4.w);
        }
        __syncthreads();
        for (int i = tid; i < FPAD; i += blockDim.x) {
            atomicAdd(&g_bnsum[i], bsum[i]);
            atomicAdd(&g_bnsq[i], bsq[i]);
        }
    }
}

// ---------------- GEMM: out[n,:] = f(in[n,:]) @ W  (f = BN-affine+ReLU) ------
// fma.rn.f32x2 packed math; IS = input row stride; optional fused BN stats.
template<int FIN, int IS, int FOUT, int NPB, bool BN_IN, bool DINV_OUT, int IB, int OB, bool STATS>
__global__ void k_gemm(const float* __restrict__ W) {
    const float* __restrict__ in = buff<IB>();
    float* __restrict__ out = buff<OB>();
    constexpr int PAIRS = FOUT / 2;
    __shared__ float2 sW[FIN * PAIRS];
    __shared__ float2 sIn[NPB * FIN];
    __shared__ float bsum[STATS ? FOUT : 1];
    __shared__ float bsq[STATS ? FOUT : 1];
    const int tid = threadIdx.x;
    const int nthreads = NPB * PAIRS;     // == blockDim.x
    for (int idx = tid; idx < FIN * PAIRS; idx += nthreads) {
        int k = idx / PAIRS, pr = idx - k * PAIRS;
        sW[idx] = make_float2(W[k * FOUT + 2 * pr], W[k * FOUT + 2 * pr + 1]);
    }
    if (STATS) {
        for (int i = tid; i < FOUT; i += nthreads) { bsum[i] = 0.f; bsq[i] = 0.f; }
    }
    const int grp = tid / PAIRS;
    const int pr  = tid - grp * PAIRS;
    float s0 = 0.f, q0 = 0.f, s1 = 0.f, q1 = 0.f;
    for (int base = blockIdx.x * NPB; base < N_NODES; base += gridDim.x * NPB) {
        __syncthreads();
        for (int idx = tid; idx < NPB * FIN; idx += nthreads) {
            int nl = idx / FIN, k = idx - nl * FIN;
            int node = base + nl;
            float v = 0.f;
            if (node < N_NODES) {
                v = in[node * IS + k];
                if (BN_IN) v = fmaxf(fmaf(v, g_bna[k], g_bnc[k]), 0.f);
            }
            sIn[idx] = make_float2(v, v);
        }
        __syncthreads();
        int node = base + grp;
        if (node < N_NODES) {
            unsigned long long a0 = 0ULL, a1 = 0ULL;
            #pragma unroll
            for (int k = 0; k < FIN; k += 2) {
                unsigned long long i0 =
                    *reinterpret_cast<const unsigned long long*>(&sIn[grp * FIN + k]);
                unsigned long long w0 =
                    *reinterpret_cast<const unsigned long long*>(&sW[k * PAIRS + pr]);
                asm("fma.rn.f32x2 %0, %1, %2, %0;" : "+l"(a0) : "l"(i0), "l"(w0));
                unsigned long long i1 =
                    *reinterpret_cast<const unsigned long long*>(&sIn[grp * FIN + k + 1]);
                unsigned long long w1 =
                    *reinterpret_cast<const unsigned long long*>(&sW[(k + 1) * PAIRS + pr]);
                asm("fma.rn.f32x2 %0, %1, %2, %0;" : "+l"(a1) : "l"(i1), "l"(w1));
            }
            unsigned long long a;
            asm("add.rn.f32x2 %0, %1, %2;" : "=l"(a) : "l"(a0), "l"(a1));
            float2 o = *reinterpret_cast<float2*>(&a);
            if (DINV_OUT) { float d = g_dinv[node]; o.x *= d; o.y *= d; }
            *reinterpret_cast<float2*>(&out[node * FOUT + 2 * pr]) = o;
            if (STATS) { s0 += o.x; q0 += o.x * o.x; s1 += o.y; q1 += o.y * o.y; }
        }
    }
    if (STATS) {
        atomicAdd(&bsum[2 * pr],     s0); atomicAdd(&bsq[2 * pr],     q0);
        atomicAdd(&bsum[2 * pr + 1], s1); atomicAdd(&bsq[2 * pr + 1], q1);
        __syncthreads();
        for (int i = tid; i < FOUT; i += nthreads) {
            atomicAdd(&g_bnsum[i], bsum[i]);
            atomicAdd(&g_bnsq[i], bsq[i]);
        }
    }
}

// ---------------- BN params: a = g*rsqrt(var+eps), c = beta - mu*a ----------
template<int F>
__global__ void k_bnparam(const float* __restrict__ g, const float* __restrict__ beta) {
    int f = threadIdx.x;
    if (f < F) {
        float inv_n = 1.0f / (float)N_NODES;
        float mu  = g_bnsum[f] * inv_n;
        float var = g_bnsq[f] * inv_n - mu * mu;
        float a = g[f] * rsqrtf(var + BN_EPS);
        g_bna[f] = a;
        g_bnc[f] = beta[f] - mu * a;
        g_bnsum[f] = 0.f;
        g_bnsq[f]  = 0.f;
    }
}

// ---------------- final apply (no ReLU): out = bn(b2) ----------------
__global__ void k_apply(float* __restrict__ out) {
    int idx = blockIdx.x * blockDim.x + threadIdx.x;
    const int total = N_NODES * 32;
    if (idx < total) {
        int f = idx & 31;
        out[idx] = fmaf(((const float*)g_b2)[idx], g_bna[f], g_bnc[f]);
    }
}

// ---------------- launcher ----------------
extern "C" void kernel_launch(void* const* d_in, const int* in_sizes, int n_in,
                              void* d_out, int out_size) {
    const float* x   = (const float*)d_in[0];
    const int*   ei  = (const int*)d_in[1];          // int32
    const float* W1  = (const float*)d_in[2];
    const float* g1  = (const float*)d_in[4];
    const float* be1 = (const float*)d_in[5];
    const float* W2  = (const float*)d_in[6];
    const float* g2  = (const float*)d_in[8];
    const float* be2 = (const float*)d_in[9];
    const float* W3  = (const float*)d_in[10];
    const float* g3  = (const float*)d_in[12];
    const float* be3 = (const float*)d_in[13];
    float* out = (float*)d_out;

    // ---- CSR build ----
    k_init<<<512, 256>>>();                               // 0
    k_count<<<(N_EDGES / 4 + 255) / 256, 256>>>(ei);      // 1
    k_scan<<<NB_SCAN, 256>>>();                           // 2
    k_scatter<<<(N_EDGES + 255) / 256, 256>>>(ei);        // 3  <- profiled

    // ---- layer 1: scale+pad(20->32), gather, GEMM 20->64 (+BN1 stats) ----
    k_scalepad<<<(N_NODES * 32 + 255) / 256, 256>>>(x);   // 4
    k_gather<32, 4, 0, 1, false><<<2048, 256>>>();        // 5: b0 -> b1
    k_gemm<20, 32, 64, 8, false, false, 1, 2, true><<<2048, 256>>>(W1); // 6: b1 -> b2
    k_bnparam<64><<<1, 64>>>(g1, be1);                    // 7

    // ---- layer 2: GEMM 64->48 (BN1+ReLU in, dinv out), gather (+BN2 stats) ----
    k_gemm<64, 64, 48, 8, true, true, 2, 0, false><<<2048, 192>>>(W2);  // 8: b2 -> b0
    k_gather<48, 2, 0, 1, true><<<2048, 256>>>();         // 9: b0 -> b1
    k_bnparam<48><<<1, 64>>>(g2, be2);                    // 10

    // ---- layer 3: GEMM 48->32 (BN2+ReLU in, dinv out), gather (+BN3 stats) ----
    k_gemm<48, 48, 32, 16, true, true, 1, 0, false><<<2048, 256>>>(W3); // 11: b1 -> b0
    k_gather<32, 4, 0, 2, true><<<2048, 256>>>();         // 12: b0 -> b2
    k_bnparam<32><<<1, 64>>>(g3, be3);                    // 13

    // ---- final BN apply ----
    k_apply<<<(N_NODES * 32 + 255) / 256, 256>>>(out);    // 14
}